// round 2
// baseline (speedup 1.0000x reference)
#include <cuda_runtime.h>

// Problem constants (fixed by the reference)
#define B_    16
#define CIN   64
#define H_    112
#define W_    112
#define COUT  128
#define KTOT  576   // CIN * 3 * 3

// Conv kernel tiling
#define NTHREADS 224
#define WSLOTS   28        // 112 / PIX
#define OCSLOTS  8
#define OCT      16        // output channels per thread
#define PIX      4         // pixels (along w) per thread
#define CCHUNK   8         // input channels staged per iteration
#define KCHUNK   (CCHUNK * 9)   // 72
#define XROW     114       // -1 .. 112 padded row
#define XROWP    116       // padded stride

// Pre-masked, transposed weights: spWT[k][oc] = weight[oc][k] * mask[oc][k]
__device__ float g_spWT[KTOT * COUT];

__global__ void prep_weights(const float* __restrict__ weight,
                             const float* __restrict__ mask) {
    int idx = blockIdx.x * blockDim.x + threadIdx.x;
    if (idx < KTOT * COUT) {
        int k  = idx >> 7;     // / COUT
        int oc = idx & 127;    // % COUT
        g_spWT[idx] = weight[oc * KTOT + k] * mask[oc * KTOT + k];
    }
}

__global__ __launch_bounds__(NTHREADS, 2)
void conv_kernel(const float* __restrict__ x,
                 const float* __restrict__ bias,
                 float* __restrict__ out) {
    __shared__ float sW[KCHUNK * COUT];          // 9216 floats = 36 KB
    __shared__ float sX[CCHUNK][3][XROWP];       // ~11 KB

    const int h      = blockIdx.x;   // output row
    const int b      = blockIdx.y;   // batch
    const int tid    = threadIdx.x;
    const int wslot  = tid % WSLOTS;
    const int ocslot = tid / WSLOTS;
    const int w0     = wslot * PIX;

    float acc[OCT][PIX];
    #pragma unroll
    for (int i = 0; i < OCT; i++)
        #pragma unroll
        for (int p = 0; p < PIX; p++) acc[i][p] = 0.0f;

    for (int cc = 0; cc < CIN / CCHUNK; cc++) {
        __syncthreads();   // protect previous chunk's SMEM reads

        // Stage weight chunk [KCHUNK][COUT] via float4 (coalesced)
        {
            const float4* gW4 = reinterpret_cast<const float4*>(g_spWT + cc * KCHUNK * COUT);
            float4* sW4 = reinterpret_cast<float4*>(sW);
            #pragma unroll 2
            for (int i = tid; i < KCHUNK * COUT / 4; i += NTHREADS)
                sW4[i] = gW4[i];
        }

        // Stage x chunk: CCHUNK channels x 3 input rows x padded width
        for (int i = tid; i < CCHUNK * 3 * XROW; i += NTHREADS) {
            int c8  = i / (3 * XROW);
            int rem = i - c8 * (3 * XROW);
            int di  = rem / XROW;
            int j   = rem - di * XROW;
            int r   = h - 1 + di;
            int w   = j - 1;
            float v = 0.0f;
            if ((unsigned)r < (unsigned)H_ && (unsigned)w < (unsigned)W_)
                v = x[(((b * CIN) + (cc * CCHUNK + c8)) * H_ + r) * W_ + w];
            sX[c8][di][j] = v;
        }
        __syncthreads();

        #pragma unroll 1
        for (int c8 = 0; c8 < CCHUNK; c8++) {
            #pragma unroll
            for (int di = 0; di < 3; di++) {
                // 6 consecutive x values cover PIX=4 pixels x 3 taps
                float v[PIX + 2];
                #pragma unroll
                for (int j = 0; j < PIX + 2; j++)
                    v[j] = sX[c8][di][w0 + j];

                #pragma unroll
                for (int dj = 0; dj < 3; dj++) {
                    const int kk = c8 * 9 + di * 3 + dj;
                    const float4* wrow =
                        reinterpret_cast<const float4*>(sW + kk * COUT) + ocslot * (OCT / 4);
                    #pragma unroll
                    for (int q = 0; q < OCT / 4; q++) {
                        float4 wv = wrow[q];
                        #pragma unroll
                        for (int p = 0; p < PIX; p++) {
                            acc[q * 4 + 0][p] += wv.x * v[p + dj];
                            acc[q * 4 + 1][p] += wv.y * v[p + dj];
                            acc[q * 4 + 2][p] += wv.z * v[p + dj];
                            acc[q * 4 + 3][p] += wv.w * v[p + dj];
                        }
                    }
                }
            }
        }
    }

    // Epilogue: add bias, vectorized store
    #pragma unroll
    for (int i = 0; i < OCT; i++) {
        const int oc = ocslot * OCT + i;
        const float bv = __ldg(bias + oc);
        float4 o;
        o.x = acc[i][0] + bv;
        o.y = acc[i][1] + bv;
        o.z = acc[i][2] + bv;
        o.w = acc[i][3] + bv;
        float* orow = out + (((size_t)(b * COUT + oc) * H_ + h) * W_);
        reinterpret_cast<float4*>(orow)[wslot] = o;
    }
}

extern "C" void kernel_launch(void* const* d_in, const int* in_sizes, int n_in,
                              void* d_out, int out_size) {
    const float* x      = (const float*)d_in[0];
    const float* weight = (const float*)d_in[1];
    const float* mask   = (const float*)d_in[2];
    const float* bias   = (const float*)d_in[3];
    float* out = (float*)d_out;

    (void)in_sizes; (void)n_in; (void)out_size;

    prep_weights<<<(KTOT * COUT + 255) / 256, 256>>>(weight, mask);

    dim3 grid(H_, B_);
    conv_kernel<<<grid, NTHREADS>>>(x, bias, out);
}

// round 3
// speedup vs baseline: 1.2173x; 1.2173x over previous
#include <cuda_runtime.h>

// Problem constants (fixed by the reference)
#define B_    16
#define CIN   64
#define H_    112
#define W_    112
#define COUT  128
#define KTOT  576   // CIN * 3 * 3

// Conv kernel tiling
#define NTHREADS 224
#define WSLOTS   28        // 112 / PIX
#define OCSLOTS  8
#define OCT      16        // output channels per thread
#define PIX      4         // pixels (along w) per thread
#define CCHUNK   8         // input channels staged per iteration
#define KCHUNK   (CCHUNK * 9)   // 72
#define XROW     114       // -1 .. 112 padded row
#define XROWP    116       // padded stride (multiple of 4 for float4 loads)

typedef unsigned long long ull;

// ---- Blackwell packed-f32x2 helpers (PTX-only; no C++ auto-fuse) ----
__device__ __forceinline__ void fma2(ull& d, ull a, ull b) {
    asm("fma.rn.f32x2 %0, %1, %2, %0;" : "+l"(d) : "l"(a), "l"(b));
}
__device__ __forceinline__ ull pack2(float v) {
    ull r;
    asm("mov.b64 %0, {%1, %1};" : "=l"(r) : "f"(v));
    return r;
}
__device__ __forceinline__ void unpack2(ull d, float& lo, float& hi) {
    asm("mov.b64 {%0, %1}, %2;" : "=f"(lo), "=f"(hi) : "l"(d));
}

// Pre-masked, transposed weights: spWT[k][oc] = weight[oc][k] * mask[oc][k]
__device__ float g_spWT[KTOT * COUT];

__global__ void prep_weights(const float* __restrict__ weight,
                             const float* __restrict__ mask) {
    int idx = blockIdx.x * blockDim.x + threadIdx.x;
    if (idx < KTOT * COUT) {
        int k  = idx >> 7;     // / COUT
        int oc = idx & 127;    // % COUT
        g_spWT[idx] = weight[oc * KTOT + k] * mask[oc * KTOT + k];
    }
}

__global__ __launch_bounds__(NTHREADS, 2)
void conv_kernel(const float* __restrict__ x,
                 const float* __restrict__ bias,
                 float* __restrict__ out) {
    __shared__ float sW[KCHUNK * COUT];          // 9216 floats = 36 KB
    __shared__ float sX[CCHUNK][3][XROWP];       // ~11 KB

    const int h      = blockIdx.x;   // output row
    const int b      = blockIdx.y;   // batch
    const int tid    = threadIdx.x;
    const int wslot  = tid % WSLOTS;
    const int ocslot = tid / WSLOTS;
    const int w0     = wslot * PIX;

    // acc2[m][p]: packed pair of output channels (ocslot*16 + 2m, +2m+1), pixel p
    ull acc2[OCT / 2][PIX];
    #pragma unroll
    for (int m = 0; m < OCT / 2; m++)
        #pragma unroll
        for (int p = 0; p < PIX; p++) acc2[m][p] = 0ull;

    for (int cc = 0; cc < CIN / CCHUNK; cc++) {
        __syncthreads();   // protect previous chunk's SMEM reads

        // Stage weight chunk [KCHUNK][COUT] via float4 (coalesced)
        {
            const float4* gW4 = reinterpret_cast<const float4*>(g_spWT + cc * KCHUNK * COUT);
            float4* sW4 = reinterpret_cast<float4*>(sW);
            #pragma unroll 2
            for (int i = tid; i < KCHUNK * COUT / 4; i += NTHREADS)
                sW4[i] = gW4[i];
        }

        // Stage x chunk: CCHUNK channels x 3 input rows x padded width
        for (int i = tid; i < CCHUNK * 3 * XROW; i += NTHREADS) {
            int c8  = i / (3 * XROW);
            int rem = i - c8 * (3 * XROW);
            int di  = rem / XROW;
            int j   = rem - di * XROW;
            int r   = h - 1 + di;
            int w   = j - 1;
            float v = 0.0f;
            if ((unsigned)r < (unsigned)H_ && (unsigned)w < (unsigned)W_)
                v = x[(((b * CIN) + (cc * CCHUNK + c8)) * H_ + r) * W_ + w];
            sX[c8][di][j] = v;
        }
        __syncthreads();

        #pragma unroll 1
        for (int c8 = 0; c8 < CCHUNK; c8++) {
            #pragma unroll
            for (int di = 0; di < 3; di++) {
                // 6 consecutive x values cover PIX=4 pixels x 3 taps.
                // float4 (conflict-free, 16B-aligned: XROWP%4==0, w0%4==0) + 2 scalars.
                float4 v03 = *reinterpret_cast<const float4*>(&sX[c8][di][w0]);
                float  v4  = sX[c8][di][w0 + 4];
                float  v5  = sX[c8][di][w0 + 5];

                ull vv[PIX + 2];
                vv[0] = pack2(v03.x); vv[1] = pack2(v03.y);
                vv[2] = pack2(v03.z); vv[3] = pack2(v03.w);
                vv[4] = pack2(v4);    vv[5] = pack2(v5);

                #pragma unroll
                for (int dj = 0; dj < 3; dj++) {
                    const int kk = c8 * 9 + di * 3 + dj;
                    // One LDS.128 yields two packed f32x2 weight pairs.
                    const ulonglong2* wrow =
                        reinterpret_cast<const ulonglong2*>(sW + kk * COUT) + ocslot * (OCT / 4);
                    #pragma unroll
                    for (int q = 0; q < OCT / 4; q++) {
                        ulonglong2 wp = wrow[q];
                        #pragma unroll
                        for (int p = 0; p < PIX; p++) {
                            fma2(acc2[2 * q + 0][p], wp.x, vv[p + dj]);
                            fma2(acc2[2 * q + 1][p], wp.y, vv[p + dj]);
                        }
                    }
                }
            }
        }
    }

    // Epilogue: unpack pairs, add bias, vectorized store
    #pragma unroll
    for (int m = 0; m < OCT / 2; m++) {
        const int oc_lo = ocslot * OCT + 2 * m;
        const int oc_hi = oc_lo + 1;
        const float blo = __ldg(bias + oc_lo);
        const float bhi = __ldg(bias + oc_hi);
        float4 olo, ohi;
        float l0, h0, l1, h1, l2, h2, l3, h3;
        unpack2(acc2[m][0], l0, h0);
        unpack2(acc2[m][1], l1, h1);
        unpack2(acc2[m][2], l2, h2);
        unpack2(acc2[m][3], l3, h3);
        olo.x = l0 + blo; olo.y = l1 + blo; olo.z = l2 + blo; olo.w = l3 + blo;
        ohi.x = h0 + bhi; ohi.y = h1 + bhi; ohi.z = h2 + bhi; ohi.w = h3 + bhi;
        float* rlo = out + (((size_t)(b * COUT + oc_lo) * H_ + h) * W_);
        float* rhi = out + (((size_t)(b * COUT + oc_hi) * H_ + h) * W_);
        reinterpret_cast<float4*>(rlo)[wslot] = olo;
        reinterpret_cast<float4*>(rhi)[wslot] = ohi;
    }
}

extern "C" void kernel_launch(void* const* d_in, const int* in_sizes, int n_in,
                              void* d_out, int out_size) {
    const float* x      = (const float*)d_in[0];
    const float* weight = (const float*)d_in[1];
    const float* mask   = (const float*)d_in[2];
    const float* bias   = (const float*)d_in[3];
    float* out = (float*)d_out;

    (void)in_sizes; (void)n_in; (void)out_size;

    prep_weights<<<(KTOT * COUT + 255) / 256, 256>>>(weight, mask);

    dim3 grid(H_, B_);
    conv_kernel<<<grid, NTHREADS>>>(x, bias, out);
}